// round 7
// baseline (speedup 1.0000x reference)
#include <cuda_runtime.h>
#include <cstdint>

// ---------------------------------------------------------------------------
// StochLinear: exact JAX threefry bits -> bit-packed CSA-popcount GEMM v4.
//   out[b,n] = 0.5*S - 0.25*(sA[b]+sB[n]) + 2048 + bias[n]      (exact fp32)
// v4: pipe-balanced CSA (4 POPC / 8 words) kept; occupancy raised to
// 2 CTAs/SM (<=128 regs) and all swizzle ALU removed via pitch-144 smem
// (natural chunk rotation, immediate-offset LDS).
// ---------------------------------------------------------------------------

#define B_DIM 4096
#define K_DIM 2048
#define N_DIM 2048
#define ROW_WORDS 512              // 8 l-slices * 64 words
#define CW   32                    // words per k-chunk (128 B)
#define NCH  (ROW_WORDS / CW)      // 16
#define PITCH 144                  // 128 B row + 16 B pad -> rotating banks
#define TILE_B (128 * PITCH)       // 18432
#define STAGE_B (2 * TILE_B)       // 36864 (A tile + B tile)
#define SMEM_BYTES (2 * STAGE_B)   // 73728

__device__ uint32_t g_Apack[(size_t)B_DIM * ROW_WORDS]; // 8 MB
__device__ uint32_t g_Wpack[(size_t)N_DIM * ROW_WORDS]; // 4 MB
__device__ int g_sA[B_DIM];
__device__ int g_sB[N_DIM];

// ---------------- Threefry-2x32 (20 rounds) --------------------------------
__host__ __device__ __forceinline__ void tf2x32(uint32_t k0, uint32_t k1,
                                                uint32_t x0, uint32_t x1,
                                                uint32_t &o0, uint32_t &o1)
{
    uint32_t ks2 = k0 ^ k1 ^ 0x1BD11BDAu;
    x0 += k0; x1 += k1;
#define TFR(r) { x0 += x1; x1 = (x1 << (r)) | (x1 >> (32 - (r))); x1 ^= x0; }
    TFR(13) TFR(15) TFR(26) TFR(6)
    x0 += k1;  x1 += ks2 + 1u;
    TFR(17) TFR(29) TFR(16) TFR(24)
    x0 += ks2; x1 += k0 + 2u;
    TFR(13) TFR(15) TFR(26) TFR(6)
    x0 += k0;  x1 += k1 + 3u;
    TFR(17) TFR(29) TFR(16) TFR(24)
    x0 += k1;  x1 += ks2 + 4u;
    TFR(13) TFR(15) TFR(26) TFR(6)
    x0 += ks2; x1 += k0 + 5u;
#undef TFR
    o0 = x0; o1 = x1;
}

// bit = (uniform(bits) < p)  ==  ((bits>>9) < ceil(p * 2^23))   (exact)
__device__ __forceinline__ uint32_t prob_to_int(float p)
{
    return (uint32_t)__float2int_ru(p * 8388608.0f);
}

// ---------------- bitgen A: (L,B,K), ctr = (l<<23)|(b<<11)|k ----------------
__global__ void __launch_bounds__(256) gen_bits_A(const float* __restrict__ x,
                                                  uint32_t k0, uint32_t k1)
{
    int t  = threadIdx.x;
    int b  = blockIdx.x * 4 + (t >> 6);
    int kw = t & 63;
    const float* xr = x + (size_t)b * K_DIM + (size_t)kw * 32;

    uint32_t words[8] = {0,0,0,0,0,0,0,0};
    for (int j = 0; j < 32; ++j) {
        float v = xr[j];
        float p = fminf(fmaxf((v + 1.0f) * 0.5f, 0.0f), 1.0f);
        uint32_t ip = prob_to_int(p);
        uint32_t base = ((uint32_t)b << 11) | (uint32_t)(kw * 32 + j);
#pragma unroll
        for (int l = 0; l < 8; ++l) {
            uint32_t o0, o1;
            tf2x32(k0, k1, 0u, ((uint32_t)l << 23) | base, o0, o1);
            if (((o0 ^ o1) >> 9) < ip) words[l] |= (1u << j);
        }
    }
    int cnt = 0;
#pragma unroll
    for (int l = 0; l < 8; ++l) {
        g_Apack[(size_t)b * ROW_WORDS + l * 64 + kw] = words[l];
        cnt += __popc(words[l]);
    }
#pragma unroll
    for (int o = 16; o > 0; o >>= 1) cnt += __shfl_down_sync(0xffffffffu, cnt, o);
    if ((t & 31) == 0) atomicAdd(&g_sA[b], cnt);
}

// ---------------- bitgen W: (L,K,N), ctr = (l<<22)|(k<<11)|n ----------------
__global__ void __launch_bounds__(256) gen_bits_W(const float* __restrict__ w,
                                                  uint32_t k0, uint32_t k1)
{
    int t  = threadIdx.x;
    int nn = blockIdx.x * 4 + (t >> 6);
    int kw = t & 63;
    const float* wr = w + (size_t)nn * K_DIM + (size_t)kw * 32;

    uint32_t words[8] = {0,0,0,0,0,0,0,0};
    for (int j = 0; j < 32; ++j) {
        float v = wr[j];
        float p = fminf(fmaxf((v + 1.0f) * 0.5f, 0.0f), 1.0f);
        uint32_t ip = prob_to_int(p);
        uint32_t kk = (uint32_t)(kw * 32 + j);
        uint32_t base = (kk << 11) | (uint32_t)nn;
#pragma unroll
        for (int l = 0; l < 8; ++l) {
            uint32_t o0, o1;
            tf2x32(k0, k1, 0u, ((uint32_t)l << 22) | base, o0, o1);
            if (((o0 ^ o1) >> 9) < ip) words[l] |= (1u << j);
        }
    }
    int cnt = 0;
#pragma unroll
    for (int l = 0; l < 8; ++l) {
        g_Wpack[(size_t)nn * ROW_WORDS + l * 64 + kw] = words[l];
        cnt += __popc(words[l]);
    }
#pragma unroll
    for (int o = 16; o > 0; o >>= 1) cnt += __shfl_down_sync(0xffffffffu, cnt, o);
    if ((t & 31) == 0) atomicAdd(&g_sB[nn], cnt);
}

__global__ void zero_counts()
{
    int i = blockIdx.x * blockDim.x + threadIdx.x;
    if (i < B_DIM) g_sA[i] = 0;
    if (i < N_DIM) g_sB[i] = 0;
}

// ---------------- popc GEMM v4 ----------------------------------------------
__device__ __forceinline__ uint32_t smem_u32(const void* p)
{
    uint32_t a;
    asm("{ .reg .u64 t; cvta.to.shared.u64 t, %1; cvt.u32.u64 %0, t; }" : "=r"(a) : "l"(p));
    return a;
}
__device__ __forceinline__ void cp16(uint32_t dst, const void* src)
{
    asm volatile("cp.async.cg.shared.global [%0], [%1], 16;" :: "r"(dst), "l"(src));
}
#define CP_COMMIT() asm volatile("cp.async.commit_group;" ::: "memory")
#define CP_WAIT1()  asm volatile("cp.async.wait_group 1;" ::: "memory")
#define CP_WAIT0()  asm volatile("cp.async.wait_group 0;" ::: "memory")

__device__ __forceinline__ uint32_t xor3(uint32_t a, uint32_t b, uint32_t c)
{
    uint32_t r;
    asm("lop3.b32 %0, %1, %2, %3, 0x96;" : "=r"(r) : "r"(a), "r"(b), "r"(c));
    return r;
}
__device__ __forceinline__ uint32_t maj3(uint32_t a, uint32_t b, uint32_t c)
{
    uint32_t r;
    asm("lop3.b32 %0, %1, %2, %3, 0xE8;" : "=r"(r) : "r"(a), "r"(b), "r"(c));
    return r;
}

// CSA 7->3 + 1 naive over 8 AND-words: 4 POPC instead of 8.
__device__ __forceinline__ void csa8(int &acc,
                                     const uint4 &a0, const uint4 &a1,
                                     const uint4 &b0, const uint4 &b1)
{
    uint32_t x0 = a0.x & b0.x, x1 = a0.y & b0.y;
    uint32_t x2 = a0.z & b0.z, x3 = a0.w & b0.w;
    uint32_t x4 = a1.x & b1.x, x5 = a1.y & b1.y;
    uint32_t x6 = a1.z & b1.z, x7 = a1.w & b1.w;
    uint32_t s0 = xor3(x0, x1, x2), c0 = maj3(x0, x1, x2);
    uint32_t s1 = xor3(x3, x4, x5), c1 = maj3(x3, x4, x5);
    uint32_t S  = xor3(s0, s1, x6), c2 = maj3(s0, s1, x6);
    uint32_t C  = xor3(c0, c1, c2), CC = maj3(c0, c1, c2);
    acc += __popc(S) + __popc(x7)
         + 2 * __popc(C) + 4 * __popc(CC);
}

__device__ __forceinline__ uint4 lds128(uint32_t addr)
{
    uint4 v;
    asm volatile("ld.shared.v4.u32 {%0,%1,%2,%3}, [%4];"
                 : "=r"(v.x), "=r"(v.y), "=r"(v.z), "=r"(v.w) : "r"(addr));
    return v;
}

__global__ void __launch_bounds__(256, 2) popc_gemm4(const float* __restrict__ bias,
                                                     float* __restrict__ out)
{
    extern __shared__ char smraw[];
    uint32_t sb = smem_u32(smraw);

    int tid = threadIdx.x;
    int tx  = tid & 15;
    int ty  = tid >> 4;
    int row0 = blockIdx.y * 128;
    int col0 = blockIdx.x * 128;

    // stage loader: row r, 16B chunk ch stored at r*PITCH + ch*16 (padding
    // rotates bank groups by row: (9r+ch)&7 — conflict-equivalent to XOR swz).
    auto load_stage = [&](int kt, int s) {
        uint32_t dst0 = sb + (uint32_t)s * STAGE_B;
#pragma unroll
        for (int q = 0; q < 8; ++q) {
            int task = tid + q * 256;          // 0..2047
            int mat  = task >> 10;             // 0 = A, 1 = B
            int rem  = task & 1023;
            int r    = rem >> 3;
            int ch   = rem & 7;
            uint32_t dst = dst0 + (uint32_t)mat * TILE_B
                         + (uint32_t)r * PITCH + (uint32_t)(ch << 4);
            const uint32_t* src = mat
                ? &g_Wpack[(size_t)(col0 + r) * ROW_WORDS + kt * CW + ch * 4]
                : &g_Apack[(size_t)(row0 + r) * ROW_WORDS + kt * CW + ch * 4];
            cp16(dst, src);
        }
    };

    int acc[8][8];
#pragma unroll
    for (int i = 0; i < 8; ++i)
#pragma unroll
        for (int j = 0; j < 8; ++j) acc[i][j] = 0;

    load_stage(0, 0); CP_COMMIT();
    load_stage(1, 1); CP_COMMIT();

    for (int kt = 0; kt < NCH; ++kt) {
        if (kt < NCH - 2) { CP_WAIT1(); } else { CP_WAIT0(); }
        __syncthreads();

        uint32_t Ab = sb + (uint32_t)(kt & 1) * STAGE_B + (uint32_t)ty * PITCH;
        uint32_t Bb = sb + (uint32_t)(kt & 1) * STAGE_B + TILE_B
                    + (uint32_t)tx * PITCH;

#pragma unroll
        for (int g = 0; g < 4; ++g) {           // 8 words = chunks 2g, 2g+1
#pragma unroll
            for (int jp = 0; jp < 4; ++jp) {    // pairs of j: hold 16 B-regs
                uint4 b00 = lds128(Bb + (2 * jp)     * (16 * PITCH) + g * 32);
                uint4 b01 = lds128(Bb + (2 * jp)     * (16 * PITCH) + g * 32 + 16);
                uint4 b10 = lds128(Bb + (2 * jp + 1) * (16 * PITCH) + g * 32);
                uint4 b11 = lds128(Bb + (2 * jp + 1) * (16 * PITCH) + g * 32 + 16);
#pragma unroll
                for (int i = 0; i < 8; ++i) {
                    uint4 a0 = lds128(Ab + i * (16 * PITCH) + g * 32);
                    uint4 a1 = lds128(Ab + i * (16 * PITCH) + g * 32 + 16);
                    csa8(acc[i][2 * jp],     a0, a1, b00, b01);
                    csa8(acc[i][2 * jp + 1], a0, a1, b10, b11);
                }
            }
        }
        __syncthreads();
        if (kt + 2 < NCH) { load_stage(kt + 2, kt & 1); CP_COMMIT(); }
    }

    // epilogue: out = 0.5*S - 0.25*(sA+sB) + 2048 + bias   (exact in fp32)
#pragma unroll
    for (int i = 0; i < 8; ++i) {
        int row = row0 + ty + 16 * i;
        float sa = (float)__ldg(&g_sA[row]);
        float* orow = out + (size_t)row * N_DIM;
#pragma unroll
        for (int j = 0; j < 8; ++j) {
            int col = col0 + tx + 16 * j;
            float s = (float)acc[i][j];
            orow[col] = 0.5f * s - 0.25f * (sa + (float)__ldg(&g_sB[col]))
                      + 2048.0f + __ldg(&bias[col]);
        }
    }
}

// ---------------------------------------------------------------------------
extern "C" void kernel_launch(void* const* d_in, const int* in_sizes, int n_in,
                              void* d_out, int out_size)
{
    const float* x    = (const float*)d_in[0];
    const float* w    = (const float*)d_in[1];
    const float* bias = (const float*)d_in[2];
    float* out        = (float*)d_out;

    // jax.random.split(jax.random.key(42)), partitionable (foldlike)
    uint32_t kA0, kA1, kB0, kB1;
    tf2x32(0u, 42u, 0u, 0u, kA0, kA1);
    tf2x32(0u, 42u, 0u, 1u, kB0, kB1);

    cudaFuncSetAttribute(popc_gemm4,
                         cudaFuncAttributeMaxDynamicSharedMemorySize, SMEM_BYTES);

    zero_counts<<<16, 256>>>();
    gen_bits_A<<<B_DIM / 4, 256>>>(x, kA0, kA1);
    gen_bits_W<<<N_DIM / 4, 256>>>(w, kB0, kB1);
    popc_gemm4<<<dim3(N_DIM / 128, B_DIM / 128), 256, SMEM_BYTES>>>(bias, out);
}

// round 8
// speedup vs baseline: 1.0846x; 1.0846x over previous
#include <cuda_runtime.h>
#include <cstdint>

// ---------------------------------------------------------------------------
// StochLinear: exact JAX threefry bits -> bit-packed CSA-popcount GEMM v5.
//   out[b,n] = 0.5*S - 0.25*(sA[b]+sB[n]) + 2048 + bias[n]      (exact fp32)
// v5: keep v3's minimal-LDS register blocking (A held across all j) but at
// 512 threads/CTA, per-thread 4x8 tile -> ~110 regs -> 4 warps/SMSP (2x v3)
// to cover dependency stalls. Pitch-144 smem (immediate-offset LDS).
// ---------------------------------------------------------------------------

#define B_DIM 4096
#define K_DIM 2048
#define N_DIM 2048
#define ROW_WORDS 512              // 8 l-slices * 64 words
#define CW   32                    // words per k-chunk (128 B)
#define NCH  (ROW_WORDS / CW)      // 16
#define PITCH 144                  // 128 B row + 16 B pad
#define TILE_B (128 * PITCH)       // 18432
#define STAGE_B (2 * TILE_B)       // 36864 (A tile + B tile)
#define SMEM_BYTES (2 * STAGE_B)   // 73728

__device__ uint32_t g_Apack[(size_t)B_DIM * ROW_WORDS]; // 8 MB
__device__ uint32_t g_Wpack[(size_t)N_DIM * ROW_WORDS]; // 4 MB
__device__ int g_sA[B_DIM];
__device__ int g_sB[N_DIM];

#ifdef __CUDA_ARCH__
#define ROTL(x, r) __funnelshift_l((x), (x), (r))
#else
#define ROTL(x, r) (((x) << (r)) | ((x) >> (32 - (r))))
#endif

// ---------------- Threefry-2x32 (20 rounds) --------------------------------
__host__ __device__ __forceinline__ void tf2x32(uint32_t k0, uint32_t k1,
                                                uint32_t x0, uint32_t x1,
                                                uint32_t &o0, uint32_t &o1)
{
    uint32_t ks2 = k0 ^ k1 ^ 0x1BD11BDAu;
    x0 += k0; x1 += k1;
#define TFR(r) { x0 += x1; x1 = ROTL(x1, r); x1 ^= x0; }
    TFR(13) TFR(15) TFR(26) TFR(6)
    x0 += k1;  x1 += ks2 + 1u;
    TFR(17) TFR(29) TFR(16) TFR(24)
    x0 += ks2; x1 += k0 + 2u;
    TFR(13) TFR(15) TFR(26) TFR(6)
    x0 += k0;  x1 += k1 + 3u;
    TFR(17) TFR(29) TFR(16) TFR(24)
    x0 += k1;  x1 += ks2 + 4u;
    TFR(13) TFR(15) TFR(26) TFR(6)
    x0 += ks2; x1 += k0 + 5u;
#undef TFR
    o0 = x0; o1 = x1;
}

// bit = (uniform(bits) < p)  ==  ((bits>>9) < ceil(p * 2^23))   (exact)
__device__ __forceinline__ uint32_t prob_to_int(float p)
{
    return (uint32_t)__float2int_ru(p * 8388608.0f);
}

// ---------------- bitgen A: (L,B,K), ctr = (l<<23)|(b<<11)|k ----------------
__global__ void __launch_bounds__(256) gen_bits_A(const float* __restrict__ x,
                                                  uint32_t k0, uint32_t k1)
{
    int t  = threadIdx.x;
    int b  = blockIdx.x * 4 + (t >> 6);
    int kw = t & 63;
    const float* xr = x + (size_t)b * K_DIM + (size_t)kw * 32;

    uint32_t words[8] = {0,0,0,0,0,0,0,0};
    for (int j = 0; j < 32; ++j) {
        float v = xr[j];
        float p = fminf(fmaxf((v + 1.0f) * 0.5f, 0.0f), 1.0f);
        uint32_t ip = prob_to_int(p);
        uint32_t base = ((uint32_t)b << 11) | (uint32_t)(kw * 32 + j);
#pragma unroll
        for (int l = 0; l < 8; ++l) {
            uint32_t o0, o1;
            tf2x32(k0, k1, 0u, ((uint32_t)l << 23) | base, o0, o1);
            if (((o0 ^ o1) >> 9) < ip) words[l] |= (1u << j);
        }
    }
    int cnt = 0;
#pragma unroll
    for (int l = 0; l < 8; ++l) {
        g_Apack[(size_t)b * ROW_WORDS + l * 64 + kw] = words[l];
        cnt += __popc(words[l]);
    }
#pragma unroll
    for (int o = 16; o > 0; o >>= 1) cnt += __shfl_down_sync(0xffffffffu, cnt, o);
    if ((t & 31) == 0) atomicAdd(&g_sA[b], cnt);
}

// ---------------- bitgen W: (L,K,N), ctr = (l<<22)|(k<<11)|n ----------------
__global__ void __launch_bounds__(256) gen_bits_W(const float* __restrict__ w,
                                                  uint32_t k0, uint32_t k1)
{
    int t  = threadIdx.x;
    int nn = blockIdx.x * 4 + (t >> 6);
    int kw = t & 63;
    const float* wr = w + (size_t)nn * K_DIM + (size_t)kw * 32;

    uint32_t words[8] = {0,0,0,0,0,0,0,0};
    for (int j = 0; j < 32; ++j) {
        float v = wr[j];
        float p = fminf(fmaxf((v + 1.0f) * 0.5f, 0.0f), 1.0f);
        uint32_t ip = prob_to_int(p);
        uint32_t kk = (uint32_t)(kw * 32 + j);
        uint32_t base = (kk << 11) | (uint32_t)nn;
#pragma unroll
        for (int l = 0; l < 8; ++l) {
            uint32_t o0, o1;
            tf2x32(k0, k1, 0u, ((uint32_t)l << 22) | base, o0, o1);
            if (((o0 ^ o1) >> 9) < ip) words[l] |= (1u << j);
        }
    }
    int cnt = 0;
#pragma unroll
    for (int l = 0; l < 8; ++l) {
        g_Wpack[(size_t)nn * ROW_WORDS + l * 64 + kw] = words[l];
        cnt += __popc(words[l]);
    }
#pragma unroll
    for (int o = 16; o > 0; o >>= 1) cnt += __shfl_down_sync(0xffffffffu, cnt, o);
    if ((t & 31) == 0) atomicAdd(&g_sB[nn], cnt);
}

__global__ void zero_counts()
{
    int i = blockIdx.x * blockDim.x + threadIdx.x;
    if (i < B_DIM) g_sA[i] = 0;
    if (i < N_DIM) g_sB[i] = 0;
}

// ---------------- popc GEMM v5 ----------------------------------------------
__device__ __forceinline__ uint32_t smem_u32(const void* p)
{
    uint32_t a;
    asm("{ .reg .u64 t; cvta.to.shared.u64 t, %1; cvt.u32.u64 %0, t; }" : "=r"(a) : "l"(p));
    return a;
}
__device__ __forceinline__ void cp16(uint32_t dst, const void* src)
{
    asm volatile("cp.async.cg.shared.global [%0], [%1], 16;" :: "r"(dst), "l"(src));
}
#define CP_COMMIT() asm volatile("cp.async.commit_group;" ::: "memory")
#define CP_WAIT1()  asm volatile("cp.async.wait_group 1;" ::: "memory")
#define CP_WAIT0()  asm volatile("cp.async.wait_group 0;" ::: "memory")

__device__ __forceinline__ uint32_t xor3(uint32_t a, uint32_t b, uint32_t c)
{
    uint32_t r;
    asm("lop3.b32 %0, %1, %2, %3, 0x96;" : "=r"(r) : "r"(a), "r"(b), "r"(c));
    return r;
}
__device__ __forceinline__ uint32_t maj3(uint32_t a, uint32_t b, uint32_t c)
{
    uint32_t r;
    asm("lop3.b32 %0, %1, %2, %3, 0xE8;" : "=r"(r) : "r"(a), "r"(b), "r"(c));
    return r;
}

// CSA 7->3 + 1 naive over 8 AND-words: 4 POPC instead of 8.
__device__ __forceinline__ void csa8(int &acc,
                                     const uint4 &a0, const uint4 &a1,
                                     const uint4 &b0, const uint4 &b1)
{
    uint32_t x0 = a0.x & b0.x, x1 = a0.y & b0.y;
    uint32_t x2 = a0.z & b0.z, x3 = a0.w & b0.w;
    uint32_t x4 = a1.x & b1.x, x5 = a1.y & b1.y;
    uint32_t x6 = a1.z & b1.z, x7 = a1.w & b1.w;
    uint32_t s0 = xor3(x0, x1, x2), c0 = maj3(x0, x1, x2);
    uint32_t s1 = xor3(x3, x4, x5), c1 = maj3(x3, x4, x5);
    uint32_t S  = xor3(s0, s1, x6), c2 = maj3(s0, s1, x6);
    uint32_t C  = xor3(c0, c1, c2), CC = maj3(c0, c1, c2);
    acc += __popc(S) + __popc(x7)
         + 2 * __popc(C) + 4 * __popc(CC);
}

__device__ __forceinline__ uint4 lds128(uint32_t addr)
{
    uint4 v;
    asm volatile("ld.shared.v4.u32 {%0,%1,%2,%3}, [%4];"
                 : "=r"(v.x), "=r"(v.y), "=r"(v.z), "=r"(v.w) : "r"(addr));
    return v;
}

__global__ void __launch_bounds__(512, 1) popc_gemm5(const float* __restrict__ bias,
                                                     float* __restrict__ out)
{
    extern __shared__ char smraw[];
    uint32_t sb = smem_u32(smraw);

    int tid = threadIdx.x;
    int tx  = tid & 15;        // 16 col-groups
    int ty  = tid >> 4;        // 32 row-groups
    int row0 = blockIdx.y * 128;
    int col0 = blockIdx.x * 128;

    // stage loader: 2048 cp16 tasks, 4 per thread; row r chunk ch at r*PITCH+ch*16
    auto load_stage = [&](int kt, int s) {
        uint32_t dst0 = sb + (uint32_t)s * STAGE_B;
#pragma unroll
        for (int q = 0; q < 4; ++q) {
            int task = tid + q * 512;          // 0..2047
            int mat  = task >> 10;             // 0 = A, 1 = B
            int rem  = task & 1023;
            int r    = rem >> 3;
            int ch   = rem & 7;
            uint32_t dst = dst0 + (uint32_t)mat * TILE_B
                         + (uint32_t)r * PITCH + (uint32_t)(ch << 4);
            const uint32_t* src = mat
                ? &g_Wpack[(size_t)(col0 + r) * ROW_WORDS + kt * CW + ch * 4]
                : &g_Apack[(size_t)(row0 + r) * ROW_WORDS + kt * CW + ch * 4];
            cp16(dst, src);
        }
    };

    int acc[4][8];
#pragma unroll
    for (int i = 0; i < 4; ++i)
#pragma unroll
        for (int j = 0; j < 8; ++j) acc[i][j] = 0;

    load_stage(0, 0); CP_COMMIT();
    load_stage(1, 1); CP_COMMIT();

    for (int kt = 0; kt < NCH; ++kt) {
        if (kt < NCH - 2) { CP_WAIT1(); } else { CP_WAIT0(); }
        __syncthreads();

        uint32_t Ab = sb + (uint32_t)(kt & 1) * STAGE_B + (uint32_t)ty * PITCH;
        uint32_t Bb = sb + (uint32_t)(kt & 1) * STAGE_B + TILE_B
                    + (uint32_t)tx * PITCH;

#pragma unroll
        for (int g = 0; g < 4; ++g) {           // 8 words = 32 B per row
            uint4 a0[4], a1[4];                 // A rows ty+32i, held across j
#pragma unroll
            for (int i = 0; i < 4; ++i) {
                uint32_t rb = Ab + i * (32 * PITCH) + g * 32;
                a0[i] = lds128(rb);
                a1[i] = lds128(rb + 16);
            }
#pragma unroll
            for (int jp = 0; jp < 4; ++jp) {    // j pairs: 2jp, 2jp+1
                uint32_t rb0 = Bb + (2 * jp)     * (16 * PITCH) + g * 32;
                uint32_t rb1 = Bb + (2 * jp + 1) * (16 * PITCH) + g * 32;
                uint4 b00 = lds128(rb0);
                uint4 b01 = lds128(rb0 + 16);
                uint4 b10 = lds128(rb1);
                uint4 b11 = lds128(rb1 + 16);
#pragma unroll
                for (int i = 0; i < 4; ++i) {
                    csa8(acc[i][2 * jp],     a0[i], a1[i], b00, b01);
                    csa8(acc[i][2 * jp + 1], a0[i], a1[i], b10, b11);
                }
            }
        }
        __syncthreads();
        if (kt + 2 < NCH) { load_stage(kt + 2, kt & 1); CP_COMMIT(); }
    }

    // epilogue: out = 0.5*S - 0.25*(sA+sB) + 2048 + bias   (exact in fp32)
#pragma unroll
    for (int i = 0; i < 4; ++i) {
        int row = row0 + ty + 32 * i;
        float sa = (float)__ldg(&g_sA[row]);
        float* orow = out + (size_t)row * N_DIM;
#pragma unroll
        for (int j = 0; j < 8; ++j) {
            int col = col0 + tx + 16 * j;
            float s = (float)acc[i][j];
            orow[col] = 0.5f * s - 0.25f * (sa + (float)__ldg(&g_sB[col]))
                      + 2048.0f + __ldg(&bias[col]);
        }
    }
}

// ---------------------------------------------------------------------------
extern "C" void kernel_launch(void* const* d_in, const int* in_sizes, int n_in,
                              void* d_out, int out_size)
{
    const float* x    = (const float*)d_in[0];
    const float* w    = (const float*)d_in[1];
    const float* bias = (const float*)d_in[2];
    float* out        = (float*)d_out;

    // jax.random.split(jax.random.key(42)), partitionable (foldlike)
    uint32_t kA0, kA1, kB0, kB1;
    tf2x32(0u, 42u, 0u, 0u, kA0, kA1);
    tf2x32(0u, 42u, 0u, 1u, kB0, kB1);

    cudaFuncSetAttribute(popc_gemm5,
                         cudaFuncAttributeMaxDynamicSharedMemorySize, SMEM_BYTES);

    zero_counts<<<16, 256>>>();
    gen_bits_A<<<B_DIM / 4, 256>>>(x, kA0, kA1);
    gen_bits_W<<<N_DIM / 4, 256>>>(w, kB0, kB1);
    popc_gemm5<<<dim3(N_DIM / 128, B_DIM / 128), 512, SMEM_BYTES>>>(bias, out);
}

// round 9
// speedup vs baseline: 1.1814x; 1.0892x over previous
#include <cuda_runtime.h>
#include <cstdint>

// ---------------------------------------------------------------------------
// StochLinear: exact JAX threefry bits -> bit-packed CSA-popcount GEMM v6.
//   out[b,n] = 0.5*S - 0.25*(sA[b]+sB[n]) + 2048 + bias[n]      (exact fp32)
// v6: csa8 core (4 POPC / 8 words, alu/xu balanced = provable optimum) at
// 256 threads, 128x64 tile, grid 1024, 2 CTAs/SM (barrier decoupling +
// halved wave-quantization tail), 3-stage cp.async, pitch-144 smem.
// ---------------------------------------------------------------------------

#define B_DIM 4096
#define K_DIM 2048
#define N_DIM 2048
#define ROW_WORDS 512              // 8 l-slices * 64 words
#define CW   32                    // words per k-chunk (128 B)
#define NCH  (ROW_WORDS / CW)      // 16
#define PITCH 144                  // 128 B row + 16 B pad
#define BM 128
#define BN 64
#define A_TILE_B (BM * PITCH)      // 18432
#define B_TILE_B (BN * PITCH)      // 9216
#define STAGE_B  (A_TILE_B + B_TILE_B)  // 27648
#define NSTG 3
#define SMEM_BYTES (NSTG * STAGE_B)     // 82944

__device__ uint32_t g_Apack[(size_t)B_DIM * ROW_WORDS]; // 8 MB
__device__ uint32_t g_Wpack[(size_t)N_DIM * ROW_WORDS]; // 4 MB
__device__ int g_sA[B_DIM];
__device__ int g_sB[N_DIM];

#ifdef __CUDA_ARCH__
#define ROTL(x, r) __funnelshift_l((x), (x), (r))
#else
#define ROTL(x, r) (((x) << (r)) | ((x) >> (32 - (r))))
#endif

// ---------------- Threefry-2x32 (20 rounds) --------------------------------
__host__ __device__ __forceinline__ void tf2x32(uint32_t k0, uint32_t k1,
                                                uint32_t x0, uint32_t x1,
                                                uint32_t &o0, uint32_t &o1)
{
    uint32_t ks2 = k0 ^ k1 ^ 0x1BD11BDAu;
    x0 += k0; x1 += k1;
#define TFR(r) { x0 += x1; x1 = ROTL(x1, r); x1 ^= x0; }
    TFR(13) TFR(15) TFR(26) TFR(6)
    x0 += k1;  x1 += ks2 + 1u;
    TFR(17) TFR(29) TFR(16) TFR(24)
    x0 += ks2; x1 += k0 + 2u;
    TFR(13) TFR(15) TFR(26) TFR(6)
    x0 += k0;  x1 += k1 + 3u;
    TFR(17) TFR(29) TFR(16) TFR(24)
    x0 += k1;  x1 += ks2 + 4u;
    TFR(13) TFR(15) TFR(26) TFR(6)
    x0 += ks2; x1 += k0 + 5u;
#undef TFR
    o0 = x0; o1 = x1;
}

// bit = (uniform(bits) < p)  ==  ((bits>>9) < ceil(p * 2^23))   (exact)
__device__ __forceinline__ uint32_t prob_to_int(float p)
{
    return (uint32_t)__float2int_ru(p * 8388608.0f);
}

// ---------------- bitgen A: (L,B,K), ctr = (l<<23)|(b<<11)|k ----------------
__global__ void __launch_bounds__(256) gen_bits_A(const float* __restrict__ x,
                                                  uint32_t k0, uint32_t k1)
{
    int t  = threadIdx.x;
    int b  = blockIdx.x * 4 + (t >> 6);
    int kw = t & 63;
    const float* xr = x + (size_t)b * K_DIM + (size_t)kw * 32;

    uint32_t words[8] = {0,0,0,0,0,0,0,0};
    for (int j = 0; j < 32; ++j) {
        float v = xr[j];
        float p = fminf(fmaxf((v + 1.0f) * 0.5f, 0.0f), 1.0f);
        uint32_t ip = prob_to_int(p);
        uint32_t base = ((uint32_t)b << 11) | (uint32_t)(kw * 32 + j);
#pragma unroll
        for (int l = 0; l < 8; ++l) {
            uint32_t o0, o1;
            tf2x32(k0, k1, 0u, ((uint32_t)l << 23) | base, o0, o1);
            if (((o0 ^ o1) >> 9) < ip) words[l] |= (1u << j);
        }
    }
    int cnt = 0;
#pragma unroll
    for (int l = 0; l < 8; ++l) {
        g_Apack[(size_t)b * ROW_WORDS + l * 64 + kw] = words[l];
        cnt += __popc(words[l]);
    }
#pragma unroll
    for (int o = 16; o > 0; o >>= 1) cnt += __shfl_down_sync(0xffffffffu, cnt, o);
    if ((t & 31) == 0) atomicAdd(&g_sA[b], cnt);
}

// ---------------- bitgen W: (L,K,N), ctr = (l<<22)|(k<<11)|n ----------------
__global__ void __launch_bounds__(256) gen_bits_W(const float* __restrict__ w,
                                                  uint32_t k0, uint32_t k1)
{
    int t  = threadIdx.x;
    int nn = blockIdx.x * 4 + (t >> 6);
    int kw = t & 63;
    const float* wr = w + (size_t)nn * K_DIM + (size_t)kw * 32;

    uint32_t words[8] = {0,0,0,0,0,0,0,0};
    for (int j = 0; j < 32; ++j) {
        float v = wr[j];
        float p = fminf(fmaxf((v + 1.0f) * 0.5f, 0.0f), 1.0f);
        uint32_t ip = prob_to_int(p);
        uint32_t kk = (uint32_t)(kw * 32 + j);
        uint32_t base = (kk << 11) | (uint32_t)nn;
#pragma unroll
        for (int l = 0; l < 8; ++l) {
            uint32_t o0, o1;
            tf2x32(k0, k1, 0u, ((uint32_t)l << 22) | base, o0, o1);
            if (((o0 ^ o1) >> 9) < ip) words[l] |= (1u << j);
        }
    }
    int cnt = 0;
#pragma unroll
    for (int l = 0; l < 8; ++l) {
        g_Wpack[(size_t)nn * ROW_WORDS + l * 64 + kw] = words[l];
        cnt += __popc(words[l]);
    }
#pragma unroll
    for (int o = 16; o > 0; o >>= 1) cnt += __shfl_down_sync(0xffffffffu, cnt, o);
    if ((t & 31) == 0) atomicAdd(&g_sB[nn], cnt);
}

__global__ void zero_counts()
{
    int i = blockIdx.x * blockDim.x + threadIdx.x;
    if (i < B_DIM) g_sA[i] = 0;
    if (i < N_DIM) g_sB[i] = 0;
}

// ---------------- popc GEMM v6 ----------------------------------------------
__device__ __forceinline__ uint32_t smem_u32(const void* p)
{
    uint32_t a;
    asm("{ .reg .u64 t; cvta.to.shared.u64 t, %1; cvt.u32.u64 %0, t; }" : "=r"(a) : "l"(p));
    return a;
}
__device__ __forceinline__ void cp16(uint32_t dst, const void* src)
{
    asm volatile("cp.async.cg.shared.global [%0], [%1], 16;" :: "r"(dst), "l"(src));
}
#define CP_COMMIT() asm volatile("cp.async.commit_group;" ::: "memory")
#define CP_WAIT2()  asm volatile("cp.async.wait_group 2;" ::: "memory")
#define CP_WAIT1()  asm volatile("cp.async.wait_group 1;" ::: "memory")
#define CP_WAIT0()  asm volatile("cp.async.wait_group 0;" ::: "memory")

__device__ __forceinline__ uint32_t xor3(uint32_t a, uint32_t b, uint32_t c)
{
    uint32_t r;
    asm("lop3.b32 %0, %1, %2, %3, 0x96;" : "=r"(r) : "r"(a), "r"(b), "r"(c));
    return r;
}
__device__ __forceinline__ uint32_t maj3(uint32_t a, uint32_t b, uint32_t c)
{
    uint32_t r;
    asm("lop3.b32 %0, %1, %2, %3, 0xE8;" : "=r"(r) : "r"(a), "r"(b), "r"(c));
    return r;
}

// CSA 7->3 + 1 naive over 8 AND-words: 4 POPC instead of 8.
__device__ __forceinline__ void csa8(int &acc,
                                     const uint4 &a0, const uint4 &a1,
                                     const uint4 &b0, const uint4 &b1)
{
    uint32_t x0 = a0.x & b0.x, x1 = a0.y & b0.y;
    uint32_t x2 = a0.z & b0.z, x3 = a0.w & b0.w;
    uint32_t x4 = a1.x & b1.x, x5 = a1.y & b1.y;
    uint32_t x6 = a1.z & b1.z, x7 = a1.w & b1.w;
    uint32_t s0 = xor3(x0, x1, x2), c0 = maj3(x0, x1, x2);
    uint32_t s1 = xor3(x3, x4, x5), c1 = maj3(x3, x4, x5);
    uint32_t S  = xor3(s0, s1, x6), c2 = maj3(s0, s1, x6);
    uint32_t C  = xor3(c0, c1, c2), CC = maj3(c0, c1, c2);
    acc += __popc(S) + __popc(x7)
         + 2 * __popc(C) + 4 * __popc(CC);
}

__device__ __forceinline__ uint4 lds128(uint32_t addr)
{
    uint4 v;
    asm volatile("ld.shared.v4.u32 {%0,%1,%2,%3}, [%4];"
                 : "=r"(v.x), "=r"(v.y), "=r"(v.z), "=r"(v.w) : "r"(addr));
    return v;
}

__global__ void __launch_bounds__(256, 2) popc_gemm6(const float* __restrict__ bias,
                                                     float* __restrict__ out)
{
    extern __shared__ char smraw[];
    uint32_t sb = smem_u32(smraw);

    int tid = threadIdx.x;
    int tx  = tid & 15;        // 16 col-groups (cols tx + 16j, j=0..3)
    int ty  = tid >> 4;        // 16 row-groups (rows ty + 16i, i=0..7)
    int row0 = blockIdx.y * BM;
    int col0 = blockIdx.x * BN;

    // stage loader: 1536 cp16 tasks (A: 1024, B: 512), 6 per thread
    auto load_stage = [&](int kt, int s) {
        uint32_t dst0 = sb + (uint32_t)s * STAGE_B;
#pragma unroll
        for (int q = 0; q < 6; ++q) {
            int task = tid + q * 256;          // 0..1535
            if (task < 1024) {
                int r = task >> 3, ch = task & 7;
                cp16(dst0 + (uint32_t)r * PITCH + (uint32_t)(ch << 4),
                     &g_Apack[(size_t)(row0 + r) * ROW_WORDS + kt * CW + ch * 4]);
            } else {
                int rem = task - 1024;
                int r = rem >> 3, ch = rem & 7;
                cp16(dst0 + A_TILE_B + (uint32_t)r * PITCH + (uint32_t)(ch << 4),
                     &g_Wpack[(size_t)(col0 + r) * ROW_WORDS + kt * CW + ch * 4]);
            }
        }
    };

    int acc[8][4];
#pragma unroll
    for (int i = 0; i < 8; ++i)
#pragma unroll
        for (int j = 0; j < 4; ++j) acc[i][j] = 0;

    load_stage(0, 0); CP_COMMIT();
    load_stage(1, 1); CP_COMMIT();
    load_stage(2, 2); CP_COMMIT();

    int stage = 0;
    for (int kt = 0; kt < NCH; ++kt) {
        if (kt < NCH - 2)      { CP_WAIT2(); }
        else if (kt == NCH - 2){ CP_WAIT1(); }
        else                   { CP_WAIT0(); }
        __syncthreads();

        uint32_t base = sb + (uint32_t)stage * STAGE_B;
        uint32_t Ab = base + (uint32_t)ty * PITCH;
        uint32_t Bb = base + A_TILE_B + (uint32_t)tx * PITCH;

#pragma unroll
        for (int g = 0; g < 4; ++g) {           // 8 words = 32 B per row
            uint4 b0[4], b1[4];                  // B cols tx+16j, held over i
#pragma unroll
            for (int j = 0; j < 4; ++j) {
                uint32_t rb = Bb + j * (16 * PITCH) + g * 32;
                b0[j] = lds128(rb);
                b1[j] = lds128(rb + 16);
            }
#pragma unroll
            for (int ih = 0; ih < 2; ++ih) {     // i in halves of 4 (regs)
                uint4 a0[4], a1[4];
#pragma unroll
                for (int i4 = 0; i4 < 4; ++i4) {
                    uint32_t rb = Ab + (ih * 4 + i4) * (16 * PITCH) + g * 32;
                    a0[i4] = lds128(rb);
                    a1[i4] = lds128(rb + 16);
                }
#pragma unroll
                for (int i4 = 0; i4 < 4; ++i4)
#pragma unroll
                    for (int j = 0; j < 4; ++j)
                        csa8(acc[ih * 4 + i4][j], a0[i4], a1[i4], b0[j], b1[j]);
            }
        }
        __syncthreads();
        if (kt + 3 < NCH) { load_stage(kt + 3, stage); CP_COMMIT(); }
        stage = (stage == NSTG - 1) ? 0 : stage + 1;
    }

    // epilogue: out = 0.5*S - 0.25*(sA+sB) + 2048 + bias   (exact in fp32)
#pragma unroll
    for (int i = 0; i < 8; ++i) {
        int row = row0 + ty + 16 * i;
        float sa = (float)__ldg(&g_sA[row]);
        float* orow = out + (size_t)row * N_DIM;
#pragma unroll
        for (int j = 0; j < 4; ++j) {
            int col = col0 + tx + 16 * j;
            float s = (float)acc[i][j];
            orow[col] = 0.5f * s - 0.25f * (sa + (float)__ldg(&g_sB[col]))
                      + 2048.0f + __ldg(&bias[col]);
        }
    }
}

// ---------------------------------------------------------------------------
extern "C" void kernel_launch(void* const* d_in, const int* in_sizes, int n_in,
                              void* d_out, int out_size)
{
    const float* x    = (const float*)d_in[0];
    const float* w    = (const float*)d_in[1];
    const float* bias = (const float*)d_in[2];
    float* out        = (float*)d_out;

    // jax.random.split(jax.random.key(42)), partitionable (foldlike)
    uint32_t kA0, kA1, kB0, kB1;
    tf2x32(0u, 42u, 0u, 0u, kA0, kA1);
    tf2x32(0u, 42u, 0u, 1u, kB0, kB1);

    cudaFuncSetAttribute(popc_gemm6,
                         cudaFuncAttributeMaxDynamicSharedMemorySize, SMEM_BYTES);

    zero_counts<<<16, 256>>>();
    gen_bits_A<<<B_DIM / 4, 256>>>(x, kA0, kA1);
    gen_bits_W<<<N_DIM / 4, 256>>>(w, kB0, kB1);
    popc_gemm6<<<dim3(N_DIM / BN, B_DIM / BM), 256, SMEM_BYTES>>>(bias, out);
}